// round 1
// baseline (speedup 1.0000x reference)
#include <cuda_runtime.h>
#include <cstdint>

#define MAX_N 50000
#define MAX_E 800000
#define MAX_B 64
#define D 128

// ---------------- scratch (static device globals; no allocation) -------------
__device__ float g_xw[MAX_N * D];      // xw1, then reused for xw2
__device__ float g_h1[MAX_N * D];      // raw conv1 output (pre-activation)
__device__ float g_a2[MAX_N * D];      // leaky(conv2 output)
__device__ int   g_cnt[MAX_N];
__device__ int   g_row_start[MAX_N + 1];
__device__ int   g_cursor[MAX_N];
__device__ int   g_perm_src[MAX_E];
__device__ float g_perm_w[MAX_E];
__device__ float g_r2[MAX_B * D];      // leaky(x0[root]) @ W2[128:]
__device__ float g_r3[MAX_B * D];      // h1[root] @ Wl[128:]

__device__ __forceinline__ float leaky(float x) { return x > 0.f ? x : 0.01f * x; }

// ---------------- CSR build --------------------------------------------------
__global__ void k_zero(int n) {
    for (int i = blockIdx.x * blockDim.x + threadIdx.x; i < n; i += gridDim.x * blockDim.x)
        g_cnt[i] = 0;
}

__global__ void k_hist(const int* __restrict__ dst, int E) {
    for (int i = blockIdx.x * blockDim.x + threadIdx.x; i < E; i += gridDim.x * blockDim.x)
        atomicAdd(&g_cnt[dst[i]], 1);
}

// single-block exclusive scan over n counts -> row_start[0..n], cursor copy
__global__ void k_scan(int n) {
    __shared__ int ssum[1024];
    const int CH = 64;                       // 1024*64 = 65536 >= n+1
    int t = threadIdx.x;
    int base = t * CH;
    int s = 0;
    for (int i = 0; i < CH; i++) {
        int idx = base + i;
        if (idx < n) s += g_cnt[idx];
    }
    ssum[t] = s;
    __syncthreads();
    for (int off = 1; off < 1024; off <<= 1) {
        int v = (t >= off) ? ssum[t - off] : 0;
        __syncthreads();
        ssum[t] += v;
        __syncthreads();
    }
    int pre = (t == 0) ? 0 : ssum[t - 1];
    for (int i = 0; i < CH; i++) {
        int idx = base + i;
        if (idx < n) {
            g_row_start[idx] = pre;
            g_cursor[idx]    = pre;
            pre += g_cnt[idx];
        } else if (idx == n) {
            g_row_start[n] = pre;
        }
    }
}

__global__ void k_scatter(const int* __restrict__ src, const int* __restrict__ dst,
                          const float* __restrict__ w, int E) {
    for (int i = blockIdx.x * blockDim.x + threadIdx.x; i < E; i += gridDim.x * blockDim.x) {
        int d   = dst[i];
        int pos = atomicAdd(&g_cursor[d], 1);
        g_perm_src[pos] = src[i];
        g_perm_w[pos]   = w[i];
    }
}

// ---------------- GEMM: C[M,128] = op(A)[M,128] @ W[0:128,:] + epilogue -------
// mode 0: plain                               (GEMM1: features @ W1)
// mode 1: A->leaky(A); C += extra[batch[row]] (GEMM2: leaky(h1) @ W2_top + r2)
// mode 2: C = leaky(C + extra[batch] + bias)  (GEMM3: a2 @ Wl_top + r3 + bl)
__global__ void __launch_bounds__(256)
k_gemm(const float* __restrict__ A, const float* __restrict__ W,
       float* __restrict__ C, int M, int mode,
       const float* __restrict__ extra, const int* __restrict__ batch,
       const float* __restrict__ bias) {
    __shared__ float Ws[64 * 128];   // 32KB: 64 k-rows of W, all 128 cols
    __shared__ float As[64 * 64];    // 16KB: 64 A-rows, 64 k-cols
    const int tid = threadIdx.x;
    const int tx  = tid & 15;        // col group: cols [tx*4..tx*4+3] and [64+tx*4..]
    const int ty  = tid >> 4;        // row group: rows [ty*4..ty*4+3]
    const int row0 = blockIdx.x * 64;

    float acc[4][8];
#pragma unroll
    for (int i = 0; i < 4; i++)
#pragma unroll
        for (int j = 0; j < 8; j++) acc[i][j] = 0.f;

    for (int kk = 0; kk < 128; kk += 64) {
        // load W rows [kk, kk+64) x 128 cols : 2048 float4
        {
            const float4* Wg  = (const float4*)(W + (size_t)kk * 128);
            float4*       Wsm = (float4*)Ws;
#pragma unroll
            for (int r = 0; r < 8; r++) Wsm[tid + r * 256] = Wg[tid + r * 256];
        }
        // load A rows [row0, row0+64), cols [kk, kk+64) : 1024 float4
        {
#pragma unroll
            for (int p = 0; p < 4; p++) {
                int idx = tid + p * 256;
                int r   = idx >> 4;
                int cq  = idx & 15;
                float4 v = make_float4(0.f, 0.f, 0.f, 0.f);
                int gr = row0 + r;
                if (gr < M) {
                    v = *(const float4*)(A + (size_t)gr * 128 + kk + cq * 4);
                    if (mode == 1) {
                        v.x = leaky(v.x); v.y = leaky(v.y);
                        v.z = leaky(v.z); v.w = leaky(v.w);
                    }
                }
                *(float4*)(As + r * 64 + cq * 4) = v;
            }
        }
        __syncthreads();
#pragma unroll 8
        for (int k = 0; k < 64; k++) {
            float4 w0 = *(const float4*)(Ws + k * 128 + tx * 4);
            float4 w1 = *(const float4*)(Ws + k * 128 + 64 + tx * 4);
#pragma unroll
            for (int i = 0; i < 4; i++) {
                float a = As[(ty * 4 + i) * 64 + k];
                acc[i][0] = fmaf(a, w0.x, acc[i][0]);
                acc[i][1] = fmaf(a, w0.y, acc[i][1]);
                acc[i][2] = fmaf(a, w0.z, acc[i][2]);
                acc[i][3] = fmaf(a, w0.w, acc[i][3]);
                acc[i][4] = fmaf(a, w1.x, acc[i][4]);
                acc[i][5] = fmaf(a, w1.y, acc[i][5]);
                acc[i][6] = fmaf(a, w1.z, acc[i][6]);
                acc[i][7] = fmaf(a, w1.w, acc[i][7]);
            }
        }
        __syncthreads();
    }

#pragma unroll
    for (int i = 0; i < 4; i++) {
        int gr = row0 + ty * 4 + i;
        if (gr >= M) continue;
        int c0 = tx * 4, c1 = 64 + tx * 4;
        float o[8];
#pragma unroll
        for (int j = 0; j < 8; j++) o[j] = acc[i][j];
        if (mode == 1) {
            const float* e = extra + (size_t)batch[gr] * 128;
            o[0] += e[c0];     o[1] += e[c0 + 1]; o[2] += e[c0 + 2]; o[3] += e[c0 + 3];
            o[4] += e[c1];     o[5] += e[c1 + 1]; o[6] += e[c1 + 2]; o[7] += e[c1 + 3];
        } else if (mode == 2) {
            const float* e = extra + (size_t)batch[gr] * 128;
            o[0] = leaky(o[0] + e[c0]     + bias[c0]);
            o[1] = leaky(o[1] + e[c0 + 1] + bias[c0 + 1]);
            o[2] = leaky(o[2] + e[c0 + 2] + bias[c0 + 2]);
            o[3] = leaky(o[3] + e[c0 + 3] + bias[c0 + 3]);
            o[4] = leaky(o[4] + e[c1]     + bias[c1]);
            o[5] = leaky(o[5] + e[c1 + 1] + bias[c1 + 1]);
            o[6] = leaky(o[6] + e[c1 + 2] + bias[c1 + 2]);
            o[7] = leaky(o[7] + e[c1 + 3] + bias[c1 + 3]);
        }
        *(float4*)(C + (size_t)gr * 128 + c0) = make_float4(o[0], o[1], o[2], o[3]);
        *(float4*)(C + (size_t)gr * 128 + c1) = make_float4(o[4], o[5], o[6], o[7]);
    }
}

// ---------------- aggregation: one warp per dst node --------------------------
// out[i] = act( sum_{e in CSR(i)} w_e * xw[src_e] + bias )
__global__ void k_agg(const float* __restrict__ xw, float* __restrict__ out,
                      const float* __restrict__ bias, int act, int n) {
    int gw   = (blockIdx.x * blockDim.x + threadIdx.x) >> 5;
    int lane = threadIdx.x & 31;
    if (gw >= n) return;
    int s = g_row_start[gw];
    int e = g_row_start[gw + 1];
    float4 acc = make_float4(0.f, 0.f, 0.f, 0.f);
    for (int i = s; i < e; i++) {
        int   src = g_perm_src[i];
        float w   = g_perm_w[i];
        float4 v  = *(const float4*)(xw + (size_t)src * D + lane * 4);
        acc.x = fmaf(w, v.x, acc.x);
        acc.y = fmaf(w, v.y, acc.y);
        acc.z = fmaf(w, v.z, acc.z);
        acc.w = fmaf(w, v.w, acc.w);
    }
    float4 b = *(const float4*)(bias + lane * 4);
    acc.x += b.x; acc.y += b.y; acc.z += b.z; acc.w += b.w;
    if (act) {
        acc.x = leaky(acc.x); acc.y = leaky(acc.y);
        acc.z = leaky(acc.z); acc.w = leaky(acc.w);
    }
    *(float4*)(out + (size_t)gw * D + lane * 4) = acc;
}

// ---------------- per-graph root projections ---------------------------------
// r2[g] = leaky(features[root_g]) @ W2[128:256]
// r3[g] = h1[root_g]              @ Wl[128:256]
__global__ void k_roots(const float* __restrict__ features, const float* __restrict__ W2,
                        const float* __restrict__ Wl, const int* __restrict__ root_idx) {
    int g = blockIdx.x, c = threadIdx.x;
    __shared__ float xf[128], xh[128];
    int r = root_idx[g];
    xf[c] = leaky(features[(size_t)r * 128 + c]);
    xh[c] = g_h1[(size_t)r * 128 + c];
    __syncthreads();
    float a2 = 0.f, a3 = 0.f;
#pragma unroll 8
    for (int k = 0; k < 128; k++) {
        a2 = fmaf(xf[k], W2[(size_t)(128 + k) * 128 + c], a2);
        a3 = fmaf(xh[k], Wl[(size_t)(128 + k) * 128 + c], a3);
    }
    g_r2[g * 128 + c] = a2;
    g_r3[g * 128 + c] = a3;
}

// ---------------- launch ------------------------------------------------------
extern "C" void kernel_launch(void* const* d_in, const int* in_sizes, int n_in,
                              void* d_out, int out_size) {
    const float* features = (const float*)d_in[0];
    const float* values   = (const float*)d_in[1];
    const float* W1       = (const float*)d_in[2];
    const float* b1       = (const float*)d_in[3];
    const float* W2       = (const float*)d_in[4];
    const float* b2       = (const float*)d_in[5];
    const float* Wl       = (const float*)d_in[6];
    const float* bl       = (const float*)d_in[7];
    const int*   adjs     = (const int*)d_in[8];
    const int*   root_idx = (const int*)d_in[9];
    const int*   batch    = (const int*)d_in[12];
    float*       out      = (float*)d_out;

    const int N = in_sizes[0] / D;
    const int E = in_sizes[1];
    const int B = in_sizes[9];
    const int* src = adjs;
    const int* dst = adjs + E;

    float *p_xw, *p_h1, *p_a2, *p_r2, *p_r3;
    cudaGetSymbolAddress((void**)&p_xw, g_xw);
    cudaGetSymbolAddress((void**)&p_h1, g_h1);
    cudaGetSymbolAddress((void**)&p_a2, g_a2);
    cudaGetSymbolAddress((void**)&p_r2, g_r2);
    cudaGetSymbolAddress((void**)&p_r3, g_r3);

    // CSR build (once; reused by both convs)
    k_zero<<<128, 256>>>(N);
    k_hist<<<512, 256>>>(dst, E);
    k_scan<<<1, 1024>>>(N);
    k_scatter<<<512, 256>>>(src, dst, values, E);

    const int gemmBlocks = (N + 63) / 64;
    const int aggBlocks  = (N * 32 + 255) / 256;

    // conv1: xw1 = features @ W1 ; h1 = agg(xw1) + b1   (raw, no activation)
    k_gemm<<<gemmBlocks, 256>>>(features, W1, p_xw, N, 0, nullptr, nullptr, nullptr);
    k_agg<<<aggBlocks, 256>>>(p_xw, p_h1, b1, 0, N);

    // per-graph root projections (needs h1)
    k_roots<<<B, 128>>>(features, W2, Wl, root_idx);

    // conv2: xw2 = leaky(h1) @ W2_top + r2[batch] ; a2 = leaky(agg(xw2) + b2)
    k_gemm<<<gemmBlocks, 256>>>(p_h1, W2, p_xw, N, 1, p_r2, batch, nullptr);
    k_agg<<<aggBlocks, 256>>>(p_xw, p_a2, b2, 1, N);

    // out = leaky(a2 @ Wl_top + r3[batch] + bl)
    k_gemm<<<gemmBlocks, 256>>>(p_a2, Wl, out, N, 2, p_r3, batch, bl);
}

// round 2
// speedup vs baseline: 1.2302x; 1.2302x over previous
#include <cuda_runtime.h>
#include <cstdint>

#define MAX_N 50000
#define MAX_E 800000
#define MAX_B 64
#define D 128

// ---------------- scratch (static device globals; no allocation) -------------
__device__ float g_xw[MAX_N * D];      // xw1, then reused for xw2
__device__ float g_h1[MAX_N * D];      // raw conv1 output (pre-activation)
__device__ float g_a2[MAX_N * D];      // leaky(conv2 output)
__device__ int   g_cnt[MAX_N];
__device__ int   g_row_start[MAX_N + 1];
__device__ int   g_cursor[MAX_N];
__device__ int   g_perm_src[MAX_E];
__device__ float g_perm_w[MAX_E];
__device__ float g_r2[MAX_B * D];      // leaky(x0[root]) @ W2[128:]
__device__ float g_r3[MAX_B * D];      // h1[root] @ Wl[128:]

__device__ __forceinline__ float leaky(float x) { return x > 0.f ? x : 0.01f * x; }

// ---------------- CSR build --------------------------------------------------
__global__ void k_hist(const int* __restrict__ dst, int E) {
    for (int i = blockIdx.x * blockDim.x + threadIdx.x; i < E; i += gridDim.x * blockDim.x)
        atomicAdd(&g_cnt[dst[i]], 1);
}

// single-block exclusive scan, counts staged in dynamic smem (coalesced I/O)
__global__ void k_scan2(int n) {
    extern __shared__ int sc[];          // n+1 ints
    __shared__ int ssum[1024];
    const int t = threadIdx.x;
    // coalesced load counts into smem
    for (int i = t; i < n; i += 1024) sc[i] = g_cnt[i];
    __syncthreads();
    const int CH = (n + 1023) >> 10;
    const int base = t * CH;
    int s = 0;
    for (int i = 0; i < CH; i++) {
        int idx = base + i;
        if (idx < n) s += sc[idx];
    }
    ssum[t] = s;
    __syncthreads();
    for (int off = 1; off < 1024; off <<= 1) {
        int v = (t >= off) ? ssum[t - off] : 0;
        __syncthreads();
        ssum[t] += v;
        __syncthreads();
    }
    int pre = (t == 0) ? 0 : ssum[t - 1];
    for (int i = 0; i < CH; i++) {
        int idx = base + i;
        if (idx < n) { int c = sc[idx]; sc[idx] = pre; pre += c; }
    }
    __syncthreads();
    if (t == 0) sc[n] = ssum[1023];
    __syncthreads();
    // coalesced write-out
    for (int i = t; i <= n; i += 1024) {
        int v = sc[i];
        g_row_start[i] = v;
        if (i < n) g_cursor[i] = v;
    }
}

__global__ void k_scatter(const int* __restrict__ src, const int* __restrict__ dst,
                          const float* __restrict__ w, int E) {
    for (int i = blockIdx.x * blockDim.x + threadIdx.x; i < E; i += gridDim.x * blockDim.x) {
        int d   = dst[i];
        int pos = atomicAdd(&g_cursor[d], 1);
        g_perm_src[pos] = src[i];
        g_perm_w[pos]   = w[i];
    }
}

// ---------------- GEMM: C[M,128] = op(A)[M,128] @ W[0:128,:] + epilogue -------
// mode 0: plain                               (GEMM1: features @ W1)
// mode 1: A->leaky(A); C += extra[batch[row]] (GEMM2: leaky(h1) @ W2_top + r2)
// mode 2: C = leaky(C + extra[batch] + bias)  (GEMM3: a2 @ Wl_top + r3 + bl)
// 128x128 block tile, K-tiles of 16, double-buffered smem, 8x8 micro-tile.
#define AS_STRIDE 132
__global__ void __launch_bounds__(256, 2)
k_gemm(const float* __restrict__ A, const float* __restrict__ W,
       float* __restrict__ C, int M, int mode,
       const float* __restrict__ extra, const int* __restrict__ batch,
       const float* __restrict__ bias) {
    __shared__ float As[2][16 * AS_STRIDE];  // [k][m], padded
    __shared__ float Ws[2][16 * 128];        // [k][n]
    const int tid = threadIdx.x;
    const int tx  = tid & 15;    // cols tx*8 .. +8
    const int ty  = tid >> 4;    // rows ty*8 .. +8
    const int row0 = blockIdx.x * 128;

    float acc[8][8];
#pragma unroll
    for (int i = 0; i < 8; i++)
#pragma unroll
        for (int j = 0; j < 8; j++) acc[i][j] = 0.f;

    // ---- load tile 0 into buffer 0 ----
#pragma unroll
    for (int p = 0; p < 2; p++) {
        int idx = tid + p * 256;
        int r = idx >> 2, kq = idx & 3;
        float4 v = make_float4(0.f, 0.f, 0.f, 0.f);
        int gr = row0 + r;
        if (gr < M) {
            v = *(const float4*)(A + (size_t)gr * 128 + kq * 4);
            if (mode == 1) { v.x = leaky(v.x); v.y = leaky(v.y); v.z = leaky(v.z); v.w = leaky(v.w); }
        }
        As[0][(kq * 4 + 0) * AS_STRIDE + r] = v.x;
        As[0][(kq * 4 + 1) * AS_STRIDE + r] = v.y;
        As[0][(kq * 4 + 2) * AS_STRIDE + r] = v.z;
        As[0][(kq * 4 + 3) * AS_STRIDE + r] = v.w;
        int k = idx >> 5, q = idx & 31;
        *(float4*)&Ws[0][k * 128 + q * 4] = *(const float4*)(W + (size_t)k * 128 + q * 4);
    }
    __syncthreads();

#pragma unroll
    for (int t = 0; t < 8; t++) {
        const int buf = t & 1;
        float4 pa[2], pw[2];
        bool   va[2];
        if (t < 7) {
            const int kk = (t + 1) * 16;
#pragma unroll
            for (int p = 0; p < 2; p++) {
                int idx = tid + p * 256;
                int r = idx >> 2, kq = idx & 3;
                int gr = row0 + r;
                va[p] = (gr < M);
                pa[p] = make_float4(0.f, 0.f, 0.f, 0.f);
                if (va[p]) pa[p] = *(const float4*)(A + (size_t)gr * 128 + kk + kq * 4);
                int k = idx >> 5, q = idx & 31;
                pw[p] = *(const float4*)(W + (size_t)(kk + k) * 128 + q * 4);
            }
        }
        // ---- compute on buf ----
#pragma unroll
        for (int k = 0; k < 16; k++) {
            float a[8], w[8];
            *(float4*)&a[0] = *(const float4*)&As[buf][k * AS_STRIDE + ty * 8];
            *(float4*)&a[4] = *(const float4*)&As[buf][k * AS_STRIDE + ty * 8 + 4];
            *(float4*)&w[0] = *(const float4*)&Ws[buf][k * 128 + tx * 8];
            *(float4*)&w[4] = *(const float4*)&Ws[buf][k * 128 + tx * 8 + 4];
#pragma unroll
            for (int i = 0; i < 8; i++)
#pragma unroll
                for (int j = 0; j < 8; j++)
                    acc[i][j] = fmaf(a[i], w[j], acc[i][j]);
        }
        // ---- store prefetched tile into buf^1 ----
        if (t < 7) {
#pragma unroll
            for (int p = 0; p < 2; p++) {
                int idx = tid + p * 256;
                int r = idx >> 2, kq = idx & 3;
                float4 v = pa[p];
                if (mode == 1 && va[p]) { v.x = leaky(v.x); v.y = leaky(v.y); v.z = leaky(v.z); v.w = leaky(v.w); }
                As[buf ^ 1][(kq * 4 + 0) * AS_STRIDE + r] = v.x;
                As[buf ^ 1][(kq * 4 + 1) * AS_STRIDE + r] = v.y;
                As[buf ^ 1][(kq * 4 + 2) * AS_STRIDE + r] = v.z;
                As[buf ^ 1][(kq * 4 + 3) * AS_STRIDE + r] = v.w;
                int k = idx >> 5, q = idx & 31;
                *(float4*)&Ws[buf ^ 1][k * 128 + q * 4] = pw[p];
            }
        }
        __syncthreads();
    }

    // ---- epilogue ----
#pragma unroll
    for (int i = 0; i < 8; i++) {
        int gr = row0 + ty * 8 + i;
        if (gr >= M) continue;
        const int c0 = tx * 8;
        float o[8];
#pragma unroll
        for (int j = 0; j < 8; j++) o[j] = acc[i][j];
        if (mode == 1) {
            const float* e = extra + (size_t)batch[gr] * 128 + c0;
#pragma unroll
            for (int j = 0; j < 8; j++) o[j] += e[j];
        } else if (mode == 2) {
            const float* e = extra + (size_t)batch[gr] * 128 + c0;
#pragma unroll
            for (int j = 0; j < 8; j++) o[j] = leaky(o[j] + e[j] + bias[c0 + j]);
        }
        *(float4*)(C + (size_t)gr * 128 + c0)     = make_float4(o[0], o[1], o[2], o[3]);
        *(float4*)(C + (size_t)gr * 128 + c0 + 4) = make_float4(o[4], o[5], o[6], o[7]);
    }
}

// ---------------- aggregation: one warp per dst node --------------------------
__global__ void k_agg(const float* __restrict__ xw, float* __restrict__ out,
                      const float* __restrict__ bias, int act, int n) {
    int gw   = (blockIdx.x * blockDim.x + threadIdx.x) >> 5;
    int lane = threadIdx.x & 31;
    if (gw >= n) return;
    int s = g_row_start[gw];
    int e = g_row_start[gw + 1];
    float4 acc0 = make_float4(0.f, 0.f, 0.f, 0.f);
    float4 acc1 = make_float4(0.f, 0.f, 0.f, 0.f);
    int i = s;
    for (; i + 1 < e; i += 2) {
        int   s0 = g_perm_src[i],     s1 = g_perm_src[i + 1];
        float w0 = g_perm_w[i],       w1 = g_perm_w[i + 1];
        float4 v0 = *(const float4*)(xw + (size_t)s0 * D + lane * 4);
        float4 v1 = *(const float4*)(xw + (size_t)s1 * D + lane * 4);
        acc0.x = fmaf(w0, v0.x, acc0.x); acc0.y = fmaf(w0, v0.y, acc0.y);
        acc0.z = fmaf(w0, v0.z, acc0.z); acc0.w = fmaf(w0, v0.w, acc0.w);
        acc1.x = fmaf(w1, v1.x, acc1.x); acc1.y = fmaf(w1, v1.y, acc1.y);
        acc1.z = fmaf(w1, v1.z, acc1.z); acc1.w = fmaf(w1, v1.w, acc1.w);
    }
    if (i < e) {
        int   s0 = g_perm_src[i];
        float w0 = g_perm_w[i];
        float4 v0 = *(const float4*)(xw + (size_t)s0 * D + lane * 4);
        acc0.x = fmaf(w0, v0.x, acc0.x); acc0.y = fmaf(w0, v0.y, acc0.y);
        acc0.z = fmaf(w0, v0.z, acc0.z); acc0.w = fmaf(w0, v0.w, acc0.w);
    }
    float4 b = *(const float4*)(bias + lane * 4);
    float4 acc = make_float4(acc0.x + acc1.x + b.x, acc0.y + acc1.y + b.y,
                             acc0.z + acc1.z + b.z, acc0.w + acc1.w + b.w);
    if (act) {
        acc.x = leaky(acc.x); acc.y = leaky(acc.y);
        acc.z = leaky(acc.z); acc.w = leaky(acc.w);
    }
    *(float4*)(out + (size_t)gw * D + lane * 4) = acc;
}

// ---------------- per-graph root projections ---------------------------------
__global__ void k_roots(const float* __restrict__ features, const float* __restrict__ W2,
                        const float* __restrict__ Wl, const int* __restrict__ root_idx) {
    int g = blockIdx.x, c = threadIdx.x;
    __shared__ float xf[128], xh[128];
    int r = root_idx[g];
    xf[c] = leaky(features[(size_t)r * 128 + c]);
    xh[c] = g_h1[(size_t)r * 128 + c];
    __syncthreads();
    float a2 = 0.f, a3 = 0.f;
#pragma unroll 8
    for (int k = 0; k < 128; k++) {
        a2 = fmaf(xf[k], W2[(size_t)(128 + k) * 128 + c], a2);
        a3 = fmaf(xh[k], Wl[(size_t)(128 + k) * 128 + c], a3);
    }
    g_r2[g * 128 + c] = a2;
    g_r3[g * 128 + c] = a3;
}

// ---------------- launch ------------------------------------------------------
extern "C" void kernel_launch(void* const* d_in, const int* in_sizes, int n_in,
                              void* d_out, int out_size) {
    const float* features = (const float*)d_in[0];
    const float* values   = (const float*)d_in[1];
    const float* W1       = (const float*)d_in[2];
    const float* b1       = (const float*)d_in[3];
    const float* W2       = (const float*)d_in[4];
    const float* b2       = (const float*)d_in[5];
    const float* Wl       = (const float*)d_in[6];
    const float* bl       = (const float*)d_in[7];
    const int*   adjs     = (const int*)d_in[8];
    const int*   root_idx = (const int*)d_in[9];
    const int*   batch    = (const int*)d_in[12];
    float*       out      = (float*)d_out;

    const int N = in_sizes[0] / D;
    const int E = in_sizes[1];
    const int B = in_sizes[9];
    const int* src = adjs;
    const int* dst = adjs + E;

    float *p_xw, *p_h1, *p_a2, *p_r2, *p_r3;
    int   *p_cnt;
    cudaGetSymbolAddress((void**)&p_xw, g_xw);
    cudaGetSymbolAddress((void**)&p_h1, g_h1);
    cudaGetSymbolAddress((void**)&p_a2, g_a2);
    cudaGetSymbolAddress((void**)&p_r2, g_r2);
    cudaGetSymbolAddress((void**)&p_r3, g_r3);
    cudaGetSymbolAddress((void**)&p_cnt, g_cnt);

    // one-time host resources (side stream + events + smem opt-in)
    static cudaStream_t s_side = nullptr;
    static cudaEvent_t  ev_fork = nullptr, ev_join = nullptr;
    if (s_side == nullptr) {
        cudaStreamCreateWithFlags(&s_side, cudaStreamNonBlocking);
        cudaEventCreateWithFlags(&ev_fork, cudaEventDisableTiming);
        cudaEventCreateWithFlags(&ev_join, cudaEventDisableTiming);
        cudaFuncSetAttribute(k_scan2, cudaFuncAttributeMaxDynamicSharedMemorySize, 220 * 1024);
    }

    const size_t scan_smem = (size_t)(N + 1) * sizeof(int);
    const int gemmBlocks = (N + 127) / 128;
    const int aggBlocks  = (N * 32 + 255) / 256;

    // ---- fork: CSR build on side stream, overlapped with GEMM1 ----
    cudaEventRecord(ev_fork, 0);
    cudaStreamWaitEvent(s_side, ev_fork, 0);
    cudaMemsetAsync(p_cnt, 0, (size_t)N * sizeof(int), s_side);
    k_hist<<<512, 256, 0, s_side>>>(dst, E);
    k_scan2<<<1, 1024, scan_smem, s_side>>>(N);
    k_scatter<<<512, 256, 0, s_side>>>(src, dst, values, E);
    cudaEventRecord(ev_join, s_side);

    // conv1 GEMM on main stream (independent of CSR)
    k_gemm<<<gemmBlocks, 256>>>(features, W1, p_xw, N, 0, nullptr, nullptr, nullptr);

    // ---- join ----
    cudaStreamWaitEvent(0, ev_join, 0);

    // conv1 aggregate: h1 = agg(xw1) + b1 (raw, no activation)
    k_agg<<<aggBlocks, 256>>>(p_xw, p_h1, b1, 0, N);

    // per-graph root projections (needs h1)
    k_roots<<<B, 128>>>(features, W2, Wl, root_idx);

    // conv2: xw2 = leaky(h1) @ W2_top + r2[batch] ; a2 = leaky(agg(xw2) + b2)
    k_gemm<<<gemmBlocks, 256>>>(p_h1, W2, p_xw, N, 1, p_r2, batch, nullptr);
    k_agg<<<aggBlocks, 256>>>(p_xw, p_a2, b2, 1, N);

    // out = leaky(a2 @ Wl_top + r3[batch] + bl)
    k_gemm<<<gemmBlocks, 256>>>(p_a2, Wl, out, N, 2, p_r3, batch, bl);
}

// round 4
// speedup vs baseline: 2.0936x; 1.7018x over previous
#include <cuda_runtime.h>
#include <cstdint>

#define MAX_N 50000
#define MAX_E 800000
#define MAX_B 64
#define D 128

// ---------------- scratch (static device globals; no allocation) -------------
__device__ float g_xw[MAX_N * D];
__device__ float g_h1[MAX_N * D];
__device__ float g_a2[MAX_N * D];
__device__ int   g_cnt[MAX_N];
__device__ int   g_row_start[MAX_N + 1];
__device__ int   g_cursor[MAX_N];
__device__ int   g_perm_src[MAX_E];
__device__ float g_perm_w[MAX_E];
__device__ float g_r2[MAX_B * D];
__device__ float g_r3[MAX_B * D];

__device__ __forceinline__ float leaky(float x) { return x > 0.f ? x : 0.01f * x; }
__device__ __forceinline__ float to_tf32(float x) {
    float r; asm("cvt.rna.tf32.f32 %0, %1;" : "=f"(r) : "f"(x)); return r;
}
__device__ __forceinline__ void mma_tf32(float& c0, float& c1, float& c2, float& c3,
                                         float a0, float a1, float a2, float a3,
                                         float b0, float b1) {
    asm volatile(
        "mma.sync.aligned.m16n8k8.row.col.f32.tf32.tf32.f32 "
        "{%0,%1,%2,%3}, {%4,%5,%6,%7}, {%8,%9}, {%0,%1,%2,%3};"
        : "+f"(c0), "+f"(c1), "+f"(c2), "+f"(c3)
        : "r"(__float_as_uint(a0)), "r"(__float_as_uint(a1)),
          "r"(__float_as_uint(a2)), "r"(__float_as_uint(a3)),
          "r"(__float_as_uint(b0)), "r"(__float_as_uint(b1)));
}

// ---------------- CSR build --------------------------------------------------
__global__ void k_hist(const int* __restrict__ dst, int E) {
    int i = blockIdx.x * blockDim.x + threadIdx.x;
    if (i < E) atomicAdd(&g_cnt[dst[i]], 1);
}

__global__ void k_scan2(int n) {
    extern __shared__ int sc[];
    __shared__ int ssum[1024];
    const int t = threadIdx.x;
    for (int i = t; i < n; i += 1024) sc[i] = g_cnt[i];
    __syncthreads();
    const int CH = (n + 1023) >> 10;
    const int base = t * CH;
    int s = 0;
    for (int i = 0; i < CH; i++) { int idx = base + i; if (idx < n) s += sc[idx]; }
    ssum[t] = s;
    __syncthreads();
    for (int off = 1; off < 1024; off <<= 1) {
        int v = (t >= off) ? ssum[t - off] : 0;
        __syncthreads(); ssum[t] += v; __syncthreads();
    }
    int pre = (t == 0) ? 0 : ssum[t - 1];
    for (int i = 0; i < CH; i++) {
        int idx = base + i;
        if (idx < n) { int c = sc[idx]; sc[idx] = pre; pre += c; }
    }
    __syncthreads();
    if (t == 0) sc[n] = ssum[1023];
    __syncthreads();
    for (int i = t; i <= n; i += 1024) {
        int v = sc[i];
        g_row_start[i] = v;
        if (i < n) g_cursor[i] = v;
    }
}

__global__ void k_scatter(const int* __restrict__ src, const int* __restrict__ dst,
                          const float* __restrict__ w, int E) {
    int i = blockIdx.x * blockDim.x + threadIdx.x;
    if (i < E) {
        int d   = dst[i];
        int pos = atomicAdd(&g_cursor[d], 1);
        g_perm_src[pos] = src[i];
        g_perm_w[pos]   = w[i];
    }
}

// ---------------- mma.sync tf32 GEMM ------------------------------------------
// C[M,128] = op(A)[M,128] @ B[128,128]  (B row-major k x n = the weight itself)
// mode 0: plain; mode 1: A->leaky(A), C += extra[batch]; mode 2: C = leaky(C+extra[batch]+bias)
#define SA 132   // A_s row stride (floats)
#define SB 136   // B_s row stride (floats)
__global__ void __launch_bounds__(256, 1)
k_mma(const float* __restrict__ A, const float* __restrict__ B,
      float* __restrict__ C, int M, int mode,
      const float* __restrict__ extra, const int* __restrict__ batch,
      const float* __restrict__ bias, int nTiles) {
    extern __shared__ float sm[];
    float* A_s = sm;                    // [128][SA]
    float* B_s = sm + 128 * SA;         // [128][SB]

    const int tid    = threadIdx.x;
    const int wid    = tid >> 5;
    const int lane   = tid & 31;
    const int g      = lane >> 2;       // group id 0..7
    const int tig    = lane & 3;        // thread in group 0..3
    const int warp_m = wid >> 2;        // 0..1 -> rows warp_m*64
    const int warp_n = wid & 3;         // 0..3 -> cols warp_n*32

    // ---- stage B (weights) once, tf32-rounded ----
#pragma unroll
    for (int i = 0; i < 16; i++) {
        int idx = tid + i * 256;        // 4096 float4
        int r = idx >> 5, c4 = idx & 31;
        float4 v = ((const float4*)B)[idx];
        v.x = to_tf32(v.x); v.y = to_tf32(v.y); v.z = to_tf32(v.z); v.w = to_tf32(v.w);
        *(float4*)(B_s + r * SB + c4 * 4) = v;
    }

    for (int t = blockIdx.x; t < nTiles; t += gridDim.x) {
        const int row0 = t * 128;
        __syncthreads();   // previous tile's readers done before overwriting A_s
        // ---- stage A tile ----
#pragma unroll
        for (int i = 0; i < 16; i++) {
            int idx = tid + i * 256;
            int r = idx >> 5, c4 = idx & 31;
            int gr = row0 + r;
            float4 v = make_float4(0.f, 0.f, 0.f, 0.f);
            if (gr < M) {
                v = *(const float4*)(A + (size_t)gr * 128 + c4 * 4);
                if (mode == 1) { v.x = leaky(v.x); v.y = leaky(v.y); v.z = leaky(v.z); v.w = leaky(v.w); }
            }
            v.x = to_tf32(v.x); v.y = to_tf32(v.y); v.z = to_tf32(v.z); v.w = to_tf32(v.w);
            *(float4*)(A_s + r * SA + c4 * 4) = v;
        }
        __syncthreads();

        // ---- compute: 4 m-tiles x 4 n-tiles x 16 k-steps ----
        float acc[4][4][4];
#pragma unroll
        for (int mt = 0; mt < 4; mt++)
#pragma unroll
            for (int nt = 0; nt < 4; nt++)
#pragma unroll
                for (int q = 0; q < 4; q++) acc[mt][nt][q] = 0.f;

        const float* Ab = A_s + (warp_m * 64 + g) * SA + tig;
        const float* Bb = B_s + tig * SB + warp_n * 32 + g;
#pragma unroll
        for (int ks = 0; ks < 16; ks++) {
            const int kc = ks * 8;
            float af[4][4];
#pragma unroll
            for (int mt = 0; mt < 4; mt++) {
                const float* ap = Ab + mt * 16 * SA + kc;
                af[mt][0] = ap[0];
                af[mt][1] = ap[8 * SA];
                af[mt][2] = ap[4];
                af[mt][3] = ap[8 * SA + 4];
            }
            float bf[4][2];
#pragma unroll
            for (int nt = 0; nt < 4; nt++) {
                const float* bp = Bb + kc * SB + nt * 8;
                bf[nt][0] = bp[0];
                bf[nt][1] = bp[4 * SB];
            }
#pragma unroll
            for (int mt = 0; mt < 4; mt++)
#pragma unroll
                for (int nt = 0; nt < 4; nt++)
                    mma_tf32(acc[mt][nt][0], acc[mt][nt][1], acc[mt][nt][2], acc[mt][nt][3],
                             af[mt][0], af[mt][1], af[mt][2], af[mt][3],
                             bf[nt][0], bf[nt][1]);
        }

        // ---- epilogue ----
#pragma unroll
        for (int mt = 0; mt < 4; mt++) {
            int r0 = row0 + warp_m * 64 + mt * 16 + g;
            int r1 = r0 + 8;
            const float* e0 = nullptr; const float* e1 = nullptr;
            if (mode != 0) {
                if (r0 < M) e0 = extra + (size_t)batch[r0] * 128;
                if (r1 < M) e1 = extra + (size_t)batch[r1] * 128;
            }
#pragma unroll
            for (int nt = 0; nt < 4; nt++) {
                int col = warp_n * 32 + nt * 8 + tig * 2;
                float o0 = acc[mt][nt][0], o1 = acc[mt][nt][1];
                float o2 = acc[mt][nt][2], o3 = acc[mt][nt][3];
                if (mode == 1) {
                    if (e0) { o0 += e0[col]; o1 += e0[col + 1]; }
                    if (e1) { o2 += e1[col]; o3 += e1[col + 1]; }
                } else if (mode == 2) {
                    float bc0 = bias[col], bc1 = bias[col + 1];
                    if (e0) { o0 = leaky(o0 + e0[col] + bc0); o1 = leaky(o1 + e0[col + 1] + bc1); }
                    if (e1) { o2 = leaky(o2 + e1[col] + bc0); o3 = leaky(o3 + e1[col + 1] + bc1); }
                }
                if (r0 < M) *(float2*)(C + (size_t)r0 * 128 + col) = make_float2(o0, o1);
                if (r1 < M) *(float2*)(C + (size_t)r1 * 128 + col) = make_float2(o2, o3);
            }
        }
    }
}

// ---------------- aggregation: one warp per dst node --------------------------
__global__ void k_agg(const float* __restrict__ xw, float* __restrict__ out,
                      const float* __restrict__ bias, int act, int n) {
    int gw   = (blockIdx.x * blockDim.x + threadIdx.x) >> 5;
    int lane = threadIdx.x & 31;
    if (gw >= n) return;
    int s = g_row_start[gw];
    int e = g_row_start[gw + 1];
    float4 acc0 = make_float4(0.f, 0.f, 0.f, 0.f);
    float4 acc1 = make_float4(0.f, 0.f, 0.f, 0.f);
    int i = s;
    for (; i + 1 < e; i += 2) {
        int   s0 = g_perm_src[i],     s1 = g_perm_src[i + 1];
        float w0 = g_perm_w[i],       w1 = g_perm_w[i + 1];
        float4 v0 = *(const float4*)(xw + (size_t)s0 * D + lane * 4);
        float4 v1 = *(const float4*)(xw + (size_t)s1 * D + lane * 4);
        acc0.x = fmaf(w0, v0.x, acc0.x); acc0.y = fmaf(w0, v0.y, acc0.y);
        acc0.z = fmaf(w0, v0.z, acc0.z); acc0.w = fmaf(w0, v0.w, acc0.w);
        acc1.x = fmaf(w1, v1.x, acc1.x); acc1.y = fmaf(w1, v1.y, acc1.y);
        acc1.z = fmaf(w1, v1.z, acc1.z); acc1.w = fmaf(w1, v1.w, acc1.w);
    }
    if (i < e) {
        int   s0 = g_perm_src[i];
        float w0 = g_perm_w[i];
        float4 v0 = *(const float4*)(xw + (size_t)s0 * D + lane * 4);
        acc0.x = fmaf(w0, v0.x, acc0.x); acc0.y = fmaf(w0, v0.y, acc0.y);
        acc0.z = fmaf(w0, v0.z, acc0.z); acc0.w = fmaf(w0, v0.w, acc0.w);
    }
    float4 b = *(const float4*)(bias + lane * 4);
    float4 acc = make_float4(acc0.x + acc1.x + b.x, acc0.y + acc1.y + b.y,
                             acc0.z + acc1.z + b.z, acc0.w + acc1.w + b.w);
    if (act) {
        acc.x = leaky(acc.x); acc.y = leaky(acc.y);
        acc.z = leaky(acc.z); acc.w = leaky(acc.w);
    }
    *(float4*)(out + (size_t)gw * D + lane * 4) = acc;
}

// ---------------- per-graph root projections ---------------------------------
__global__ void k_roots(const float* __restrict__ features, const float* __restrict__ W2,
                        const float* __restrict__ Wl, const int* __restrict__ root_idx) {
    int g = blockIdx.x, c = threadIdx.x;
    __shared__ float xf[128], xh[128];
    int r = root_idx[g];
    xf[c] = leaky(features[(size_t)r * 128 + c]);
    xh[c] = g_h1[(size_t)r * 128 + c];
    __syncthreads();
    float a2 = 0.f, a3 = 0.f;
#pragma unroll 8
    for (int k = 0; k < 128; k++) {
        a2 = fmaf(xf[k], W2[(size_t)(128 + k) * 128 + c], a2);
        a3 = fmaf(xh[k], Wl[(size_t)(128 + k) * 128 + c], a3);
    }
    g_r2[g * 128 + c] = a2;
    g_r3[g * 128 + c] = a3;
}

// ---------------- launch ------------------------------------------------------
extern "C" void kernel_launch(void* const* d_in, const int* in_sizes, int n_in,
                              void* d_out, int out_size) {
    const float* features = (const float*)d_in[0];
    const float* values   = (const float*)d_in[1];
    const float* W1       = (const float*)d_in[2];
    const float* b1       = (const float*)d_in[3];
    const float* W2       = (const float*)d_in[4];
    const float* b2       = (const float*)d_in[5];
    const float* Wl       = (const float*)d_in[6];
    const float* bl       = (const float*)d_in[7];
    const int*   adjs     = (const int*)d_in[8];
    const int*   root_idx = (const int*)d_in[9];
    const int*   batch    = (const int*)d_in[12];
    float*       out      = (float*)d_out;

    const int N = in_sizes[0] / D;
    const int E = in_sizes[1];
    const int B = in_sizes[9];
    const int* src = adjs;
    const int* dst = adjs + E;

    float *p_xw, *p_h1, *p_a2, *p_r2, *p_r3;
    int   *p_cnt;
    cudaGetSymbolAddress((void**)&p_xw, g_xw);
    cudaGetSymbolAddress((void**)&p_h1, g_h1);
    cudaGetSymbolAddress((void**)&p_a2, g_a2);
    cudaGetSymbolAddress((void**)&p_r2, g_r2);
    cudaGetSymbolAddress((void**)&p_r3, g_r3);
    cudaGetSymbolAddress((void**)&p_cnt, g_cnt);

    static cudaStream_t s_side = nullptr;
    static cudaEvent_t  ev_fork = nullptr, ev_join = nullptr;
    if (s_side == nullptr) {
        cudaStreamCreateWithFlags(&s_side, cudaStreamNonBlocking);
        cudaEventCreateWithFlags(&ev_fork, cudaEventDisableTiming);
        cudaEventCreateWithFlags(&ev_join, cudaEventDisableTiming);
        cudaFuncSetAttribute(k_scan2, cudaFuncAttributeMaxDynamicSharedMemorySize, 220 * 1024);
        cudaFuncSetAttribute(k_mma, cudaFuncAttributeMaxDynamicSharedMemorySize, 140 * 1024);
    }

    const size_t scan_smem = (size_t)(N + 1) * sizeof(int);
    const size_t mma_smem  = (size_t)(128 * SA + 128 * SB) * sizeof(float);  // 137216
    const int nTiles    = (N + 127) / 128;
    const int mmaGrid   = nTiles < 148 ? nTiles : 148;
    const int aggBlocks = (N * 32 + 255) / 256;

    // ---- fork: CSR build on side stream, overlapped with GEMM1 ----
    cudaEventRecord(ev_fork, 0);
    cudaStreamWaitEvent(s_side, ev_fork, 0);
    cudaMemsetAsync(p_cnt, 0, (size_t)N * sizeof(int), s_side);
    k_hist<<<(E + 255) / 256, 256, 0, s_side>>>(dst, E);
    k_scan2<<<1, 1024, scan_smem, s_side>>>(N);
    k_scatter<<<(E + 255) / 256, 256, 0, s_side>>>(src, dst, values, E);
    cudaEventRecord(ev_join, s_side);

    // conv1 GEMM on main stream (independent of CSR)
    k_mma<<<mmaGrid, 256, mma_smem>>>(features, W1, p_xw, N, 0, nullptr, nullptr, nullptr, nTiles);

    // ---- join ----
    cudaStreamWaitEvent(0, ev_join, 0);

    // conv1 aggregate: h1 = agg(xw1) + b1 (raw)
    k_agg<<<aggBlocks, 256>>>(p_xw, p_h1, b1, 0, N);

    // per-graph root projections
    k_roots<<<B, 128>>>(features, W2, Wl, root_idx);

    // conv2: xw2 = leaky(h1) @ W2_top + r2[batch] ; a2 = leaky(agg(xw2) + b2)
    k_mma<<<mmaGrid, 256, mma_smem>>>(p_h1, W2, p_xw, N, 1, p_r2, batch, nullptr, nTiles);
    k_agg<<<aggBlocks, 256>>>(p_xw, p_a2, b2, 1, N);

    // final linear: out = leaky(a2 @ Wl_top + r3[batch] + bl)
    k_mma<<<mmaGrid, 256, mma_smem>>>(p_a2, Wl, out, N, 2, p_r3, batch, bl, nTiles);
}